// round 5
// baseline (speedup 1.0000x reference)
#include <cuda_runtime.h>

#define NPTS    8192
#define BATCH   4
#define NPOINT  2048
#define NSAMPLE 32
#define CIN     67
#define COUT    128
#define KTOT    (CIN * NSAMPLE)   // 2144
#define R2      0.04f

typedef unsigned long long ull;

// scratch: ball query neighbor indices (B, NPOINT, NSAMPLE)
__device__ int g_ball_idx[BATCH * NPOINT * NSAMPLE];

// ---------------------------------------------------------------------------
// packed f32x2 helpers (sm_103a) — add/sub/mul only (no packed min/max exists)
// ---------------------------------------------------------------------------
__device__ __forceinline__ ull f2pk(float lo, float hi) {
    ull r; asm("mov.b64 %0, {%1, %2};" : "=l"(r) : "f"(lo), "f"(hi)); return r;
}
__device__ __forceinline__ void f2unpk(ull v, float& lo, float& hi) {
    asm("mov.b64 {%0, %1}, %2;" : "=f"(lo), "=f"(hi) : "l"(v));
}
__device__ __forceinline__ ull f2add(ull a, ull b) {
    ull r; asm("add.rn.f32x2 %0, %1, %2;" : "=l"(r) : "l"(a), "l"(b)); return r;
}
__device__ __forceinline__ ull f2sub(ull a, ull b) {
    ull r; asm("sub.rn.f32x2 %0, %1, %2;" : "=l"(r) : "l"(a), "l"(b)); return r;
}
__device__ __forceinline__ ull f2mul(ull a, ull b) {
    ull r; asm("mul.rn.f32x2 %0, %1, %2;" : "=l"(r) : "l"(a), "l"(b)); return r;
}

// ---------------------------------------------------------------------------
// Kernel 1: Furthest Point Sampling. One CTA (512 thr) per batch.
// Packed f32x2 distance arithmetic (bit-identical to reference rounding),
// scalar fminf dist update, pairwise FMNMX max tree. Own-max rescan overlaps
// redux.max; index tie-breaks via ballot+ffs+shfl (ownership index-ordered).
// ---------------------------------------------------------------------------
#define FPS_T   512
#define PPT     (NPTS / FPS_T)    // 16 points per thread
#define NPAIR   (PPT / 2)         // 8 packed pairs

__global__ void __launch_bounds__(FPS_T, 1)
fps_kernel(const float* __restrict__ points, float* __restrict__ new_xyz)
{
    extern __shared__ float4 pts4[];                   // NPTS float4 = 128 KB
    __shared__ ull redw[2][FPS_T / 32];                // parity double-buffer

    const int b = blockIdx.x;
    const int t = threadIdx.x;
    const int lane = t & 31;
    const int w = t >> 5;
    const float* P = points + (size_t)b * NPTS * 3;

    for (int i = t; i < NPTS; i += FPS_T)
        pts4[i] = make_float4(P[3 * i], P[3 * i + 1], P[3 * i + 2], 0.0f);
    __syncthreads();

    const int base = t * PPT;
    ull px2[NPAIR], py2[NPAIR], pz2[NPAIR];
    float dist[PPT];
#pragma unroll
    for (int j = 0; j < NPAIR; j++) {
        float4 a = pts4[base + 2 * j];
        float4 c = pts4[base + 2 * j + 1];
        px2[j] = f2pk(a.x, c.x);
        py2[j] = f2pk(a.y, c.y);
        pz2[j] = f2pk(a.z, c.z);
    }
#pragma unroll
    for (int j = 0; j < PPT; j++) dist[j] = 1e10f;

    float4 q0 = pts4[0];
    float lx = q0.x, ly = q0.y, lz = q0.z;
    if (t == 0) {
        float* o = new_xyz + (size_t)b * NPOINT * 3;
        o[0] = lx; o[1] = ly; o[2] = lz;
    }

    for (int iter = 1; iter < NPOINT; ++iter) {
        const int par = iter & 1;
        const ull lxp = f2pk(lx, lx);
        const ull lyp = f2pk(ly, ly);
        const ull lzp = f2pk(lz, lz);

        float mx[PPT];
#pragma unroll
        for (int j = 0; j < NPAIR; j++) {
            // identical arithmetic to reference: (dx*dx + dy*dy) + dz*dz, rn
            ull dx = f2sub(px2[j], lxp);
            ull dy = f2sub(py2[j], lyp);
            ull dz = f2sub(pz2[j], lzp);
            ull d2 = f2add(f2add(f2mul(dx, dx), f2mul(dy, dy)), f2mul(dz, dz));
            float d0, d1;
            f2unpk(d2, d0, d1);
            float n0 = fminf(dist[2 * j + 0], d0);
            float n1 = fminf(dist[2 * j + 1], d1);
            dist[2 * j + 0] = n0;
            dist[2 * j + 1] = n1;
            mx[2 * j + 0] = n0;
            mx[2 * j + 1] = n1;
        }
        // pairwise max tree (depth 4) instead of a serial chain
#pragma unroll
        for (int s = PPT / 2; s > 0; s >>= 1)
#pragma unroll
            for (int k = 0; k < s; k++) mx[k] = fmaxf(mx[k], mx[k + s]);
        const unsigned bb = __float_as_uint(mx[0]);

        // warp max (dist >= 0 -> uint order == float order); rescan below
        // compares against the thread's OWN max, so it overlaps redux latency
        const unsigned wm = __reduce_max_sync(0xffffffffu, bb);

        int c[PPT];
#pragma unroll
        for (int j = 0; j < PPT; j++)
            c[j] = (__float_as_uint(dist[j]) == bb) ? base + j : 0x7fffffff;
#pragma unroll
        for (int s = PPT / 2; s > 0; s >>= 1)
#pragma unroll
            for (int k = 0; k < s; k++) c[k] = min(c[k], c[k + s]);
        const int gi = c[0];   // lowest local index matching own max

        // lowest lane with bb==wm holds the warp's lowest winning index
        const unsigned mk = __ballot_sync(0xffffffffu, bb == wm);
        const int src = __ffs(mk) - 1;
        const int wi = __shfl_sync(0xffffffffu, gi, src);
        if (lane == 0)
            redw[par][w] = ((ull)wm << 32) | (unsigned)wi;
        __syncthreads();                               // the ONLY barrier

        // every warp reduces the 16 warp results (warp order == index order)
        const ull v = (lane < FPS_T / 32) ? redw[par][lane] : 0ull;
        const unsigned hv = (unsigned)(v >> 32);
        const unsigned lv = (unsigned)v;
        const unsigned gmv = __reduce_max_sync(0xffffffffu, hv);
        const unsigned mk2 = __ballot_sync(0xffffffffu, hv == gmv);
        const int s2 = __ffs(mk2) - 1;
        const int best = __shfl_sync(0xffffffffu, (int)lv, s2);

        float4 q = pts4[best];
        lx = q.x; ly = q.y; lz = q.z;
        if (t == 0) {
            float* o = new_xyz + ((size_t)b * NPOINT + iter) * 3;
            o[0] = lx; o[1] = ly; o[2] = lz;
        }
    }
}

// ---------------------------------------------------------------------------
// Kernel 2: ball query. One warp per center. Collects the first NSAMPLE
// point indices (ascending) with d2 < R2, padded with the first found index.
// ---------------------------------------------------------------------------
__global__ void __launch_bounds__(256)
ball_kernel(const float* __restrict__ points, const float* __restrict__ new_xyz,
            int* __restrict__ out_idx)
{
    const int gw = (blockIdx.x * blockDim.x + threadIdx.x) >> 5;
    const int lane = threadIdx.x & 31;
    if (gw >= BATCH * NPOINT) return;
    const int b = gw / NPOINT;
    const float* P = points + (size_t)b * NPTS * 3;

    const float cx = new_xyz[gw * 3 + 0];
    const float cy = new_xyz[gw * 3 + 1];
    const float cz = new_xyz[gw * 3 + 2];
    int* row = out_idx + (size_t)gw * NSAMPLE;

    int filled = 0;
    int first = 0;
    for (int basei = 0; basei < NPTS; basei += 32) {
        const int i = basei + lane;
        float x = P[i * 3 + 0], y = P[i * 3 + 1], z = P[i * 3 + 2];
        float dx = __fadd_rn(x, -cx);
        float dy = __fadd_rn(y, -cy);
        float dz = __fadd_rn(z, -cz);
        float d2 = __fadd_rn(__fadd_rn(__fmul_rn(dx, dx), __fmul_rn(dy, dy)),
                             __fmul_rn(dz, dz));
        unsigned m = __ballot_sync(0xffffffffu, d2 < R2);
        if (filled == 0 && m) first = basei + __ffs(m) - 1;
        if (d2 < R2) {
            int pos = filled + __popc(m & ((1u << lane) - 1));
            if (pos < NSAMPLE) row[pos] = i;
        }
        filled += __popc(m);
        if (filled >= NSAMPLE) break;
    }
    for (int j = filled + lane; j < NSAMPLE; j += 32) row[j] = first;
}

// ---------------------------------------------------------------------------
// Kernel 3: fused gather + pointwise conv.
// conv[b,p,o] = sum_{s,c} g[b,p,s,c] * w[o,c,s], k = c*32+s (matches W layout).
// Block = 64 points x 128 outputs. Chunk 0 = xyz channels (kend=96),
// chunks 1..16 = 4 feature channels each via one LDG.128 (kend=128).
// Inner loop 4-kk blocked with float4 LDS; s_w padded to 132 floats/row
// (132 % 32 == 4 -> 8-lane LDS.128 phases hit banks 4l..4l+3: conflict-free).
// ---------------------------------------------------------------------------
#define PT 64
#define WPAD 132

__global__ void __launch_bounds__(256, 1)
conv_kernel(const float* __restrict__ points,
            const float* __restrict__ features,
            const float* __restrict__ weight,
            const float* __restrict__ new_xyz,
            const int* __restrict__ ball_idx,
            float* __restrict__ conv_out)
{
    extern __shared__ char smraw[];
    float* s_g   = (float*)smraw;                  // [64][128]
    float* s_w   = s_g + PT * 128;                 // [128][WPAD]
    int*   s_idx = (int*)(s_w + COUT * WPAD);      // [64][32]
    float* s_ctr = (float*)(s_idx + PT * NSAMPLE); // [64][3]

    const int t = threadIdx.x;
    const int b  = blockIdx.x >> 5;                // 32 tiles per batch
    const int p0 = (blockIdx.x & 31) * PT;
    const float* P = points   + (size_t)b * NPTS * 3;
    const float4* F4 = (const float4*)(features + (size_t)b * NPTS * 64);

    for (int i = t; i < PT * NSAMPLE; i += 256)
        s_idx[i] = ball_idx[((size_t)b * NPOINT + p0) * NSAMPLE + i];
    for (int i = t; i < PT * 3; i += 256)
        s_ctr[i] = new_xyz[((size_t)b * NPOINT + p0) * 3 + i];
    __syncthreads();

    int myidx[8];
#pragma unroll
    for (int q = 0; q < 8; q++) myidx[q] = s_idx[q * 256 + t];

    const int og = t & 31;
    const int pg = t >> 5;
    float acc[8][4];
#pragma unroll
    for (int i = 0; i < 8; i++)
#pragma unroll
        for (int j = 0; j < 4; j++) acc[i][j] = 0.0f;

    for (int chunk = 0; chunk < 17; chunk++) {
        const int c0   = (chunk == 0) ? 0 : (4 * chunk - 1);
        const int kend = (chunk == 0) ? 96 : 128;
        __syncthreads();   // previous compute done before overwrite

        // stage g tile: 64p x 32s, layout [p][ci*32 + s]
        if (chunk == 0) {
#pragma unroll
            for (int q = 0; q < 8; q++) {
                const int pr = q * 256 + t;
                const int p = pr >> 5, s = pr & 31;
                const int idx = myidx[q];
#pragma unroll
                for (int ci = 0; ci < 3; ci++)
                    s_g[p * 128 + ci * 32 + s] =
                        P[idx * 3 + ci] - s_ctr[p * 3 + ci];
            }
        } else {
            const int m = chunk - 1;
#pragma unroll
            for (int q = 0; q < 8; q++) {
                const int pr = q * 256 + t;
                const int p = pr >> 5, s = pr & 31;
                float4 fv = F4[(size_t)myidx[q] * 16 + m];
                s_g[p * 128 +  0 + s] = fv.x;
                s_g[p * 128 + 32 + s] = fv.y;
                s_g[p * 128 + 64 + s] = fv.z;
                s_g[p * 128 + 96 + s] = fv.w;
            }
        }
        // stage W tile: 128 o x kend k, float4
#pragma unroll
        for (int q = 0; q < 16; q++) {
            const int task = q * 256 + t;
            const int o = task >> 5;
            const int k4 = (task & 31) * 4;
            if (k4 < kend) {
                float4 wv = *(const float4*)(weight + (size_t)o * KTOT + c0 * 32 + k4);
                *(float4*)&s_w[o * WPAD + k4] = wv;
            }
        }
        __syncthreads();

        for (int kk = 0; kk < kend; kk += 4) {
            float4 w0 = *(const float4*)&s_w[(og +  0) * WPAD + kk];
            float4 w1 = *(const float4*)&s_w[(og + 32) * WPAD + kk];
            float4 w2 = *(const float4*)&s_w[(og + 64) * WPAD + kk];
            float4 w3 = *(const float4*)&s_w[(og + 96) * WPAD + kk];
#pragma unroll
            for (int i = 0; i < 8; i++) {
                float4 g = *(const float4*)&s_g[(pg * 8 + i) * 128 + kk];
                acc[i][0] = fmaf(g.x, w0.x, fmaf(g.y, w0.y, fmaf(g.z, w0.z, fmaf(g.w, w0.w, acc[i][0]))));
                acc[i][1] = fmaf(g.x, w1.x, fmaf(g.y, w1.y, fmaf(g.z, w1.z, fmaf(g.w, w1.w, acc[i][1]))));
                acc[i][2] = fmaf(g.x, w2.x, fmaf(g.y, w2.y, fmaf(g.z, w2.z, fmaf(g.w, w2.w, acc[i][2]))));
                acc[i][3] = fmaf(g.x, w3.x, fmaf(g.y, w3.y, fmaf(g.z, w3.z, fmaf(g.w, w3.w, acc[i][3]))));
            }
        }
    }

#pragma unroll
    for (int i = 0; i < 8; i++) {
        const int p = p0 + pg * 8 + i;
        float* dst = conv_out + ((size_t)b * NPOINT + p) * COUT;
        dst[og +  0] = acc[i][0];
        dst[og + 32] = acc[i][1];
        dst[og + 64] = acc[i][2];
        dst[og + 96] = acc[i][3];
    }
}

// ---------------------------------------------------------------------------

extern "C" void kernel_launch(void* const* d_in, const int* in_sizes, int n_in,
                              void* d_out, int out_size)
{
    const float* points   = (const float*)d_in[0];
    const float* features = (const float*)d_in[1];
    const float* weight   = (const float*)d_in[2];
    float* out = (float*)d_out;
    float* new_xyz = out;                            // B*NPOINT*3
    float* conv    = out + BATCH * NPOINT * 3;       // B*NPOINT*COUT

    const int fps_smem  = NPTS * sizeof(float4);                          // 128 KB
    const int conv_smem = (PT * 128 + COUT * WPAD + PT * 3) * sizeof(float)
                        + PT * NSAMPLE * sizeof(int);                     // ~109 KB

    cudaFuncSetAttribute(fps_kernel,  cudaFuncAttributeMaxDynamicSharedMemorySize, fps_smem);
    cudaFuncSetAttribute(conv_kernel, cudaFuncAttributeMaxDynamicSharedMemorySize, conv_smem);

    int* ball_ptr = nullptr;
    cudaGetSymbolAddress((void**)&ball_ptr, g_ball_idx);

    fps_kernel<<<BATCH, FPS_T, fps_smem>>>(points, new_xyz);
    ball_kernel<<<(BATCH * NPOINT) / 8, 256>>>(points, new_xyz, ball_ptr);
    conv_kernel<<<BATCH * (NPOINT / PT), 256, conv_smem>>>(
        points, features, weight, new_xyz, ball_ptr, conv);
}

// round 6
// speedup vs baseline: 1.1313x; 1.1313x over previous
#include <cuda_runtime.h>

#define NPTS    8192
#define BATCH   4
#define NPOINT  2048
#define NSAMPLE 32
#define CIN     67
#define COUT    128
#define KTOT    (CIN * NSAMPLE)   // 2144
#define R2      0.04f

#define TPB     512
#define PPT     (NPTS / TPB)      // 16 points per thread (FPS)
#define NPAIR   (PPT / 2)         // 8 packed pairs

#define WPB     35                // worker CTAs per batch
#define NWORK   (WPB * BATCH)     // 140 workers
#define TILE    16                // centers per conv tile
#define TILES_PER_B (NPOINT / TILE)   // 128
#define WPAD    132               // s_w row pitch (132 % 32 == 4 -> conflict-free)

typedef unsigned long long ull;

// progress flags: centers completed per batch. Reset by reset_kernel each call.
__device__ int g_progress[BATCH];

// ---------------------------------------------------------------------------
// packed f32x2 helpers (sm_103a) — add/sub/mul only
// ---------------------------------------------------------------------------
__device__ __forceinline__ ull f2pk(float lo, float hi) {
    ull r; asm("mov.b64 %0, {%1, %2};" : "=l"(r) : "f"(lo), "f"(hi)); return r;
}
__device__ __forceinline__ void f2unpk(ull v, float& lo, float& hi) {
    asm("mov.b64 {%0, %1}, %2;" : "=f"(lo), "=f"(hi) : "l"(v));
}
__device__ __forceinline__ ull f2add(ull a, ull b) {
    ull r; asm("add.rn.f32x2 %0, %1, %2;" : "=l"(r) : "l"(a), "l"(b)); return r;
}
__device__ __forceinline__ ull f2sub(ull a, ull b) {
    ull r; asm("sub.rn.f32x2 %0, %1, %2;" : "=l"(r) : "l"(a), "l"(b)); return r;
}
__device__ __forceinline__ ull f2mul(ull a, ull b) {
    ull r; asm("mul.rn.f32x2 %0, %1, %2;" : "=l"(r) : "l"(a), "l"(b)); return r;
}

__global__ void reset_kernel() {
    if (threadIdx.x < BATCH) g_progress[threadIdx.x] = 0;
}

// ---------------------------------------------------------------------------
// Fused persistent kernel. Blocks 0..3: FPS (R3-exact variant, measured-best).
// Blocks 4..143: workers. Each worker handles 16-center tiles round-robin:
// spin-wait on progress, ball query (1 warp per center, rows in SMEM),
// then the 16p x 128o conv tile.
// ---------------------------------------------------------------------------
__global__ void __launch_bounds__(TPB, 1)
fused_kernel(const float* __restrict__ points,
             const float* __restrict__ features,
             const float* __restrict__ weight,
             float* __restrict__ new_xyz,
             float* __restrict__ conv_out)
{
    extern __shared__ char smraw[];
    __shared__ ull redw[2][TPB / 32];

    const int t = threadIdx.x;
    const int lane = t & 31;
    const int w = t >> 5;

    if (blockIdx.x < BATCH) {
        // ======================= FPS role =======================
        const int b = blockIdx.x;
        float4* pts4 = (float4*)smraw;           // NPTS float4 = 128 KB
        const float* P = points + (size_t)b * NPTS * 3;

        for (int i = t; i < NPTS; i += TPB)
            pts4[i] = make_float4(P[3 * i], P[3 * i + 1], P[3 * i + 2], 0.0f);
        __syncthreads();

        const int base = t * PPT;
        ull px2[NPAIR], py2[NPAIR], pz2[NPAIR];
        float dist[PPT];
#pragma unroll
        for (int j = 0; j < NPAIR; j++) {
            float4 a = pts4[base + 2 * j];
            float4 c = pts4[base + 2 * j + 1];
            px2[j] = f2pk(a.x, c.x);
            py2[j] = f2pk(a.y, c.y);
            pz2[j] = f2pk(a.z, c.z);
        }
#pragma unroll
        for (int j = 0; j < PPT; j++) dist[j] = 1e10f;

        float4 q0 = pts4[0];
        float lx = q0.x, ly = q0.y, lz = q0.z;
        if (t == 0) {
            float* o = new_xyz + (size_t)b * NPOINT * 3;
            o[0] = lx; o[1] = ly; o[2] = lz;
        }

        for (int iter = 1; iter < NPOINT; ++iter) {
            const int par = iter & 1;
            const ull lxp = f2pk(lx, lx);
            const ull lyp = f2pk(ly, ly);
            const ull lzp = f2pk(lz, lz);

            float bv = -1.0f;
#pragma unroll
            for (int j = 0; j < NPAIR; j++) {
                // identical arithmetic to reference: (dx*dx+dy*dy)+dz*dz, rn
                ull dx = f2sub(px2[j], lxp);
                ull dy = f2sub(py2[j], lyp);
                ull dz = f2sub(pz2[j], lzp);
                ull d2 = f2add(f2add(f2mul(dx, dx), f2mul(dy, dy)), f2mul(dz, dz));
                float d0, d1;
                f2unpk(d2, d0, d1);
                float n0 = fminf(dist[2 * j + 0], d0);
                float n1 = fminf(dist[2 * j + 1], d1);
                dist[2 * j + 0] = n0;
                dist[2 * j + 1] = n1;
                bv = fmaxf(bv, fmaxf(n0, n1));
            }

            // warp max (dist >= 0 -> uint order == float order)
            const unsigned bb = __float_as_uint(bv);
            const unsigned wm = __reduce_max_sync(0xffffffffu, bb);

            // winner-only rescan (predicated off for non-winning threads)
            unsigned li = 0x7fffffffu;
            if (bb == wm) {
#pragma unroll
                for (int j = PPT - 1; j >= 0; j--)
                    if (__float_as_uint(dist[j]) == wm) li = base + j;
            }
            const unsigned wi_ = __reduce_min_sync(0xffffffffu, li);
            if (lane == 0)
                redw[par][w] = ((ull)wm << 32) | wi_;
            __syncthreads();                               // the ONLY barrier

            // every warp reduces the 16 warp results
            const ull v = (lane < TPB / 32) ? redw[par][lane] : 0ull;
            const unsigned hv = (unsigned)(v >> 32);
            const unsigned lv = (unsigned)v;
            const unsigned gmv = __reduce_max_sync(0xffffffffu, hv);
            const unsigned ii = (hv == gmv) ? lv : 0x7fffffffu;
            const int best = (int)__reduce_min_sync(0xffffffffu, ii);

            float4 q = pts4[best];
            lx = q.x; ly = q.y; lz = q.z;
            if (t == 0) {
                float* o = new_xyz + ((size_t)b * NPOINT + iter) * 3;
                o[0] = lx; o[1] = ly; o[2] = lz;
                if ((iter & 31) == 31)
                    asm volatile("st.release.gpu.global.u32 [%0], %1;"
                                 :: "l"(g_progress + b), "r"(iter + 1) : "memory");
            }
        }
    } else {
        // ======================= worker role =======================
        const int wi = blockIdx.x - BATCH;       // 0..NWORK-1
        const int b = wi / WPB;
        const int wslot = wi - b * WPB;

        float* s_g   = (float*)smraw;                   // [16][128]
        float* s_w   = s_g + TILE * 128;                // [128][WPAD]
        int*   s_idx = (int*)(s_w + COUT * WPAD);       // [16][32]
        float* s_ctr = (float*)(s_idx + TILE * NSAMPLE);// [16][3]

        const float*  P  = points + (size_t)b * NPTS * 3;
        const float4* F4 = (const float4*)(features + (size_t)b * NPTS * 64);
        const int og = lane;            // o in {og, og+32, og+64, og+96}
        const int pg = w;               // point within tile (0..15)

        for (int tile = wslot; tile < TILES_PER_B; tile += WPB) {
            const int p0 = tile * TILE;

            // wait until centers [p0, p0+TILE) exist
            if (t == 0) {
                const int target = p0 + TILE;
                unsigned pr;
                while (true) {
                    asm volatile("ld.acquire.gpu.global.u32 %0, [%1];"
                                 : "=r"(pr) : "l"(g_progress + b) : "memory");
                    if ((int)pr >= target) break;
                    __nanosleep(256);
                }
            }
            __syncthreads();

            // ---- ball query: warp w handles center p0+w ----
            {
                const size_t crow = ((size_t)b * NPOINT + p0 + w) * 3;
                const float cx = new_xyz[crow + 0];
                const float cy = new_xyz[crow + 1];
                const float cz = new_xyz[crow + 2];
                if (lane < 3) s_ctr[w * 3 + lane] = new_xyz[crow + lane];

                int* row = s_idx + w * NSAMPLE;
                int filled = 0, first = 0;
                for (int basei = 0; basei < NPTS; basei += 32) {
                    const int i = basei + lane;
                    float dx = __fadd_rn(P[i * 3 + 0], -cx);
                    float dy = __fadd_rn(P[i * 3 + 1], -cy);
                    float dz = __fadd_rn(P[i * 3 + 2], -cz);
                    float d2 = __fadd_rn(__fadd_rn(__fmul_rn(dx, dx), __fmul_rn(dy, dy)),
                                         __fmul_rn(dz, dz));
                    unsigned m = __ballot_sync(0xffffffffu, d2 < R2);
                    if (filled == 0 && m) first = basei + __ffs(m) - 1;
                    if (d2 < R2) {
                        int pos = filled + __popc(m & ((1u << lane) - 1));
                        if (pos < NSAMPLE) row[pos] = i;
                    }
                    filled += __popc(m);
                    if (filled >= NSAMPLE) break;
                }
                for (int j = filled + lane; j < NSAMPLE; j += 32) row[j] = first;
            }
            __syncthreads();

            const int myidx = s_idx[pg * NSAMPLE + lane];   // (p=pg, s=lane)

            // ---- conv tile: 16p x 128o, K streamed in 17 chunks ----
            float acc[4] = {0.0f, 0.0f, 0.0f, 0.0f};
            for (int chunk = 0; chunk < 17; chunk++) {
                const int c0   = (chunk == 0) ? 0 : (4 * chunk - 1);
                const int kend = (chunk == 0) ? 96 : 128;
                __syncthreads();

                // g stage: one (p,s) pair per thread
                if (chunk == 0) {
#pragma unroll
                    for (int ci = 0; ci < 3; ci++)
                        s_g[pg * 128 + ci * 32 + lane] =
                            P[myidx * 3 + ci] - s_ctr[pg * 3 + ci];
                } else {
                    float4 fv = F4[(size_t)myidx * 16 + (chunk - 1)];
                    s_g[pg * 128 +  0 + lane] = fv.x;
                    s_g[pg * 128 + 32 + lane] = fv.y;
                    s_g[pg * 128 + 64 + lane] = fv.z;
                    s_g[pg * 128 + 96 + lane] = fv.w;
                }
                // w stage: 128 o x kend k
#pragma unroll
                for (int q = 0; q < 8; q++) {
                    const int task = q * TPB + t;
                    const int o = task >> 5;
                    const int k4 = (task & 31) * 4;
                    if (k4 < kend)
                        *(float4*)&s_w[o * WPAD + k4] =
                            *(const float4*)(weight + (size_t)o * KTOT + c0 * 32 + k4);
                }
                __syncthreads();

                for (int kk = 0; kk < kend; kk += 4) {
                    float4 w0 = *(const float4*)&s_w[(og +  0) * WPAD + kk];
                    float4 w1 = *(const float4*)&s_w[(og + 32) * WPAD + kk];
                    float4 w2 = *(const float4*)&s_w[(og + 64) * WPAD + kk];
                    float4 w3 = *(const float4*)&s_w[(og + 96) * WPAD + kk];
                    float4 g  = *(const float4*)&s_g[pg * 128 + kk];
                    acc[0] = fmaf(g.x, w0.x, fmaf(g.y, w0.y, fmaf(g.z, w0.z, fmaf(g.w, w0.w, acc[0]))));
                    acc[1] = fmaf(g.x, w1.x, fmaf(g.y, w1.y, fmaf(g.z, w1.z, fmaf(g.w, w1.w, acc[1]))));
                    acc[2] = fmaf(g.x, w2.x, fmaf(g.y, w2.y, fmaf(g.z, w2.z, fmaf(g.w, w2.w, acc[2]))));
                    acc[3] = fmaf(g.x, w3.x, fmaf(g.y, w3.y, fmaf(g.z, w3.z, fmaf(g.w, w3.w, acc[3]))));
                }
            }

            float* dst = conv_out + ((size_t)b * NPOINT + p0 + pg) * COUT;
            dst[og +  0] = acc[0];
            dst[og + 32] = acc[1];
            dst[og + 64] = acc[2];
            dst[og + 96] = acc[3];
        }
    }
}

// ---------------------------------------------------------------------------

extern "C" void kernel_launch(void* const* d_in, const int* in_sizes, int n_in,
                              void* d_out, int out_size)
{
    const float* points   = (const float*)d_in[0];
    const float* features = (const float*)d_in[1];
    const float* weight   = (const float*)d_in[2];
    float* out = (float*)d_out;
    float* new_xyz = out;                            // B*NPOINT*3
    float* conv    = out + BATCH * NPOINT * 3;       // B*NPOINT*COUT

    const int smem = NPTS * sizeof(float4);          // 128 KB (worker fits too)
    cudaFuncSetAttribute(fused_kernel, cudaFuncAttributeMaxDynamicSharedMemorySize, smem);

    reset_kernel<<<1, 32>>>();
    fused_kernel<<<BATCH + NWORK, TPB, smem>>>(points, features, weight, new_xyz, conv);
}